// round 5
// baseline (speedup 1.0000x reference)
#include <cuda_runtime.h>
#include <cuda.h>
#include <cstdint>

#define BB 8
#define SS 1024
#define HH 128

// ---------------- scratch ----------------
__device__ float g_scores[(size_t)BB * SS * SS];        // e = exp(score)

// ---------------- helpers ----------------
__device__ __forceinline__ void ffma2(unsigned long long &acc, unsigned long long a, unsigned long long b) {
    asm("fma.rn.f32x2 %0, %1, %2, %0;" : "+l"(acc) : "l"(a), "l"(b));
}
__device__ __forceinline__ void unpack2(unsigned long long p, float &lo, float &hi) {
    asm("mov.b64 {%0, %1}, %2;" : "=f"(lo), "=f"(hi) : "l"(p));
}
__device__ __forceinline__ void cpa16(uint32_t s, const void* g) {
    asm volatile("cp.async.cg.shared.global [%0], [%1], 16;" :: "r"(s), "l"(g));
}
#define CP_COMMIT() asm volatile("cp.async.commit_group;" ::: "memory")
#define CP_WAIT1()  asm volatile("cp.async.wait_group 1;" ::: "memory")

#define MBARRIER_INIT(a, n) \
    asm volatile("mbarrier.init.shared.b64 [%0], %1;" :: "r"(a), "r"(n) : "memory")
#define MBARRIER_EXPECT_TX(a, tx) \
    asm volatile("mbarrier.arrive.expect_tx.shared.b64 _, [%0], %1;" :: "r"(a), "r"(tx) : "memory")
#define MBARRIER_ARRIVE(a) \
    asm volatile("mbarrier.arrive.release.cta.shared.b64 _, [%0];" :: "r"(a) : "memory")
#define MBARRIER_WAIT(a, ph) do { \
    asm volatile("{\n\t.reg .pred P;\n\tWL%=:\n\t" \
        "mbarrier.try_wait.parity.acquire.cta.shared::cta.b64 P, [%0], %1, 0x989680;\n\t" \
        "@P bra.uni WD%=;\n\tbra.uni WL%=;\n\tWD%=:\n\t}" \
        :: "r"(a), "r"(ph) : "memory"); \
} while (0)
#define TMA_LOAD_3D(smem_addr, map, cx, cy, cz, mbar) \
    asm volatile("cp.async.bulk.tensor.3d.shared::cta.global.tile.mbarrier::complete_tx::bytes " \
        "[%0], [%1, {%2, %3, %4}], [%5];" \
        :: "r"((uint32_t)(smem_addr)), "l"(map), "r"((int)(cx)), "r"((int)(cy)), "r"((int)(cz)), \
           "r"((uint32_t)(mbar)) : "memory")

// =====================================================================
// Kernel A (persistent): e[b,i,j] = exp(sum_h x[b,j,h]*rel[i,j,h]).
// grid=148, each block streams ~7 tiles through ONE continuous 4-stage TMA
// pipeline (no drain between tiles). 256 thr = 32 j x 4 ig x 2 h-halves,
// thread tile 8i x 8b x 4h. Dedicated epilogue scratch outside the pipeline.
// =====================================================================
#define TIA 32
#define TJA 32
#define HCA 8
#define NTILES 1024
#define GRIDA 148
#define NSTAGE 4
#define REL_BYTES (TIA * TJA * HCA * 4)   // 32768
#define X_BYTES   (BB * TJA * HCA * 4)    // 8192
#define STAGE_BYTES (REL_BYTES + X_BYTES) // 40960
#define SCR_OFF (1024 + NSTAGE * STAGE_BYTES)      // 164864
#define SMEMA (SCR_OFF + 32768)                    // 197632

__global__ void __launch_bounds__(256, 1)
scores_kernel(const __grid_constant__ CUtensorMap tmr,
              const __grid_constant__ CUtensorMap tmx,
              float* __restrict__ scores) {
    extern __shared__ __align__(1024) char sm[];
    const uint32_t sbase = (uint32_t)__cvta_generic_to_shared(sm);
    const uint32_t mb = sbase;
    const int t  = threadIdx.x;
    const int j  = t & 31;
    const int g  = t >> 5;
    const int hg = g >> 2;       // h-half
    const int ig = g & 3;        // i-group (8 rows)
    const int bid = blockIdx.x;
    const int fo = (16 * hg) ^ (((j >> 2) & 1) << 4);  // SW32 xor, const/thread

    int ntiles = 0;
    for (int tile = bid; tile < NTILES; tile += GRIDA) ntiles++;
    const int total = ntiles * 16;

    if (t == 0) {
#pragma unroll
        for (int s = 0; s < NSTAGE; s++) {
            MBARRIER_INIT(mb + s * 16, 1);       // full
            MBARRIER_INIT(mb + s * 16 + 8, 256); // empty
        }
    }
    __syncthreads();

    if (t == 0) {
#pragma unroll
        for (int n = 0; n < NSTAGE; n++) {       // first 4 chunks are tile 0 of this block
            uint32_t fb = mb + n * 16;
            uint32_t dst = sbase + 1024 + n * STAGE_BYTES;
            const int i0n = (bid >> 5) * TIA, j0n = (bid & 31) * TJA;
            MBARRIER_EXPECT_TX(fb, STAGE_BYTES);
            TMA_LOAD_3D(dst, &tmr, n * HCA, j0n, i0n, fb);
            TMA_LOAD_3D(dst + REL_BYTES, &tmx, n * HCA, j0n, 0, fb);
        }
    }

    unsigned long long acc[8][8] = {};   // 8 i x 8 b, f32x2 each (half-h)
    float* scr0 = (float*)(sm + SCR_OFF);            // hg1 partials, q0..3
    float* scr1 = (float*)(sm + SCR_OFF + 16384);    // hg0 partials, q4..7

    for (int cg = 0; cg < total; cg++) {
        const int slot = cg & 3;
        const int ph = (cg >> 2) & 1;
        MBARRIER_WAIT(mb + slot * 16, ph);

        const char* st = sm + 1024 + slot * STAGE_BYTES;
        const char* rb = st + ((ig * 8) * TJA + j) * 32 + fo;
        const char* xb = st + REL_BYTES + (size_t)j * 32 + fo;

        ulonglong2 xv[8], rv[8];
#pragma unroll
        for (int q = 0; q < 8; q++)
            xv[q] = *(const ulonglong2*)(xb + q * (TJA * 32));
#pragma unroll
        for (int p = 0; p < 8; p++)
            rv[p] = *(const ulonglong2*)(rb + p * (TJA * 32));

        MBARRIER_ARRIVE(mb + slot * 16 + 8);

        // rotating producer: warp (cg&7) issues chunk cg+NSTAGE (may be next tile)
        {
            const int n = cg + NSTAGE;
            if (n < total && g == (cg & 7)) {
                const int eph = ((n >> 2) + 1) & 1;
                MBARRIER_WAIT(mb + slot * 16 + 8, eph);
                if (j == 0) {
                    const int tile_n = bid + (n >> 4) * GRIDA;
                    const int cn = n & 15;
                    const int i0n = (tile_n >> 5) * TIA, j0n = (tile_n & 31) * TJA;
                    uint32_t fb = mb + slot * 16;
                    uint32_t dst = sbase + 1024 + slot * STAGE_BYTES;
                    MBARRIER_EXPECT_TX(fb, STAGE_BYTES);
                    TMA_LOAD_3D(dst, &tmr, cn * HCA, j0n, i0n, fb);
                    TMA_LOAD_3D(dst + REL_BYTES, &tmx, cn * HCA, j0n, 0, fb);
                }
            }
        }

#pragma unroll
        for (int p = 0; p < 8; p++)
#pragma unroll
            for (int q = 0; q < 8; q++) {
                ffma2(acc[p][q], rv[p].x, xv[q].x);
                ffma2(acc[p][q], rv[p].y, xv[q].y);
            }

        if ((cg & 15) == 15) {
            // ---- tile epilogue (scratch is outside pipeline buffers) ----
            const int tile = bid + (cg >> 4) * GRIDA;
            const int i0 = (tile >> 5) * TIA, j0 = (tile & 31) * TJA;
            __syncthreads();
            if (hg == 1) {
#pragma unroll
                for (int p = 0; p < 8; p++)
#pragma unroll
                    for (int q = 0; q < 4; q++) {
                        float lo, hi; unpack2(acc[p][q], lo, hi);
                        scr0[((ig * 8 + p) * 4 + q) * 32 + j] = lo + hi;
                    }
            } else {
#pragma unroll
                for (int p = 0; p < 8; p++)
#pragma unroll
                    for (int q = 4; q < 8; q++) {
                        float lo, hi; unpack2(acc[p][q], lo, hi);
                        scr1[((ig * 8 + p) * 4 + (q - 4)) * 32 + j] = lo + hi;
                    }
            }
            __syncthreads();
            const int qbase = hg ? 4 : 0;
            const float* other = hg ? scr1 : scr0;
#pragma unroll
            for (int p = 0; p < 8; p++) {
                const int i = i0 + ig * 8 + p;
#pragma unroll
                for (int qq = 0; qq < 4; qq++) {
                    const int q = qbase + qq;
                    float lo, hi; unpack2(acc[p][q], lo, hi);
                    float v = lo + hi + other[((ig * 8 + p) * 4 + qq) * 32 + j];
                    // no max-subtract: |score| <= ~70, exp safe in f32
                    scores[((size_t)q * SS + i) * SS + j0 + j] = __expf(v);
                }
            }
            __syncthreads();
#pragma unroll
            for (int p = 0; p < 8; p++)
#pragma unroll
                for (int q = 0; q < 8; q++) acc[p][q] = 0ull;
        }
    }
}

// =====================================================================
// Kernel B: out[b,i,h] = (sum_j e[b,i,j]*x[b,j,h]) / (sum_j e[b,i,j])
// Denominator fused: row sums accumulated from the w tiles in-register.
// 256 thr, MTB=64 -> grid 16x8 = 128 blocks, one wave.
// =====================================================================
#define MTB 64
#define KTB 32
#define NCHB (SS / KTB)
#define WROW 36
#define XROW 132
#define WF (MTB * WROW)
#define XFB (KTB * XROW)
#define BUFBF (WF + XFB)
#define NBUFB 3

__global__ void __launch_bounds__(256, 1)
out_kernel(const float* __restrict__ w,
           const float* __restrict__ x,
           float* __restrict__ out) {
    extern __shared__ float smB[];
    const int t  = threadIdx.x;
    const int tx = t & 31;       // h quad
    const int ty = t >> 5;       // 8 groups of 8 i-rows
    const int b  = blockIdx.y;
    const int m0 = blockIdx.x * MTB;
    const float* wb = w + (size_t)b * SS * SS;
    const float* xb = x + (size_t)b * SS * HH;
    const uint32_t sbase = (uint32_t)__cvta_generic_to_shared(smB);

    auto stage = [&](int c, int s) {
        uint32_t bbase = sbase + (uint32_t)s * (BUFBF * 4);
#pragma unroll
        for (int k = 0; k < 2; k++) {
            int idx = t + k * 256;
            int f4 = idx & 7, row = idx >> 3;
            cpa16(bbase + (uint32_t)(row * WROW + f4 * 4) * 4,
                  wb + (size_t)(m0 + row) * SS + c * KTB + f4 * 4);
        }
#pragma unroll
        for (int k = 0; k < 4; k++) {
            int idx = t + k * 256;
            int f4 = idx & 31, row = idx >> 5;
            cpa16(bbase + (uint32_t)(WF + row * XROW + f4 * 4) * 4,
                  xb + (size_t)(c * KTB + row) * HH + f4 * 4);
        }
    };

    stage(0, 0); CP_COMMIT();
    stage(1, 1); CP_COMMIT();

    unsigned long long acc[8][2] = {};
    float wsum[8];
#pragma unroll
    for (int p = 0; p < 8; p++) wsum[p] = 0.f;

    int buf = 0;
    for (int c = 0; c < NCHB; c++) {
        CP_WAIT1();
        __syncthreads();
        if (c + 2 < NCHB) {
            int nb = buf + 2; if (nb >= NBUFB) nb -= NBUFB;
            stage(c + 2, nb);
        }
        CP_COMMIT();

        const float* wsb = smB + (size_t)buf * BUFBF;
        const float* xsb = wsb + WF;
#pragma unroll
        for (int j4 = 0; j4 < KTB / 4; j4++) {
            float4 wv[8];
#pragma unroll
            for (int p = 0; p < 8; p++)
                wv[p] = *reinterpret_cast<const float4*>(wsb + (ty * 8 + p) * WROW + j4 * 4);
#pragma unroll
            for (int p = 0; p < 8; p++)
                wsum[p] += (wv[p].x + wv[p].y) + (wv[p].z + wv[p].w);
#pragma unroll
            for (int jj = 0; jj < 4; jj++) {
                ulonglong2 xv = *reinterpret_cast<const ulonglong2*>(xsb + (j4 * 4 + jj) * XROW + tx * 4);
#pragma unroll
                for (int p = 0; p < 8; p++) {
                    float wval = (jj == 0) ? wv[p].x : (jj == 1) ? wv[p].y : (jj == 2) ? wv[p].z : wv[p].w;
                    unsigned long long wp;
                    asm("mov.b64 %0, {%1, %1};" : "=l"(wp) : "f"(wval));
                    ffma2(acc[p][0], wp, xv.x);
                    ffma2(acc[p][1], wp, xv.y);
                }
            }
        }
        buf++; if (buf == NBUFB) buf = 0;
    }

#pragma unroll
    for (int p = 0; p < 8; p++) {
        float inv = 1.0f / wsum[p];
        float4 o;
        unpack2(acc[p][0], o.x, o.y);
        unpack2(acc[p][1], o.z, o.w);
        o.x *= inv; o.y *= inv; o.z *= inv; o.w *= inv;
        *reinterpret_cast<float4*>(out + ((size_t)b * SS + m0 + ty * 8 + p) * HH + tx * 4) = o;
    }
}

// ---------------- launch ----------------
typedef CUresult (*EncodeFn)(CUtensorMap*, CUtensorMapDataType, cuuint32_t, void*,
                             const cuuint64_t*, const cuuint64_t*, const cuuint32_t*,
                             const cuuint32_t*, CUtensorMapInterleave, CUtensorMapSwizzle,
                             CUtensorMapL2promotion, CUtensorMapFloatOOBfill);

extern "C" void kernel_launch(void* const* d_in, const int* in_sizes, int n_in,
                              void* d_out, int out_size) {
    const float* x   = (const float*)d_in[0];   // (8, 1024, 128) f32
    const float* rel = (const float*)d_in[1];   // (1024, 1024, 128) f32
    float* out = (float*)d_out;

    float* scores = nullptr;
    cudaGetSymbolAddress((void**)&scores, g_scores);

    EncodeFn enc = nullptr;
    cudaDriverEntryPointQueryResult qr;
    cudaGetDriverEntryPoint("cuTensorMapEncodeTiled", (void**)&enc, cudaEnableDefault, &qr);

    CUtensorMap tmr, tmx;
    {
        cuuint64_t dims[3]    = {HH, SS, SS};
        cuuint64_t strides[2] = {HH * 4ull, (cuuint64_t)SS * HH * 4ull};
        cuuint32_t box[3]     = {HCA, TJA, TIA};
        cuuint32_t es[3]      = {1, 1, 1};
        enc(&tmr, CU_TENSOR_MAP_DATA_TYPE_FLOAT32, 3, (void*)rel, dims, strides, box, es,
            CU_TENSOR_MAP_INTERLEAVE_NONE, CU_TENSOR_MAP_SWIZZLE_32B,
            CU_TENSOR_MAP_L2_PROMOTION_L2_128B, CU_TENSOR_MAP_FLOAT_OOB_FILL_NONE);
    }
    {
        cuuint64_t dims[3]    = {HH, SS, BB};
        cuuint64_t strides[2] = {HH * 4ull, (cuuint64_t)SS * HH * 4ull};
        cuuint32_t box[3]     = {HCA, TJA, BB};
        cuuint32_t es[3]      = {1, 1, 1};
        enc(&tmx, CU_TENSOR_MAP_DATA_TYPE_FLOAT32, 3, (void*)x, dims, strides, box, es,
            CU_TENSOR_MAP_INTERLEAVE_NONE, CU_TENSOR_MAP_SWIZZLE_32B,
            CU_TENSOR_MAP_L2_PROMOTION_L2_128B, CU_TENSOR_MAP_FLOAT_OOB_FILL_NONE);
    }

    cudaFuncSetAttribute(scores_kernel, cudaFuncAttributeMaxDynamicSharedMemorySize, SMEMA);
    scores_kernel<<<GRIDA, 256, SMEMA>>>(tmr, tmx, scores);

    const int smB_bytes = NBUFB * BUFBF * 4;
    cudaFuncSetAttribute(out_kernel, cudaFuncAttributeMaxDynamicSharedMemorySize, smB_bytes);
    out_kernel<<<dim3(SS / MTB, BB), 256, smB_bytes>>>(scores, x, out);
}

// round 6
// speedup vs baseline: 2.1208x; 2.1208x over previous
#include <cuda_runtime.h>
#include <cuda.h>
#include <cstdint>

#define BB 8
#define SS 1024
#define HH 128

// ---------------- scratch ----------------
__device__ float g_scores[(size_t)BB * SS * SS];        // e = exp(score)
__device__ float g_xT[(size_t)BB * HH * SS];            // x transposed: [b][h][j]

// ---------------- helpers ----------------
__device__ __forceinline__ void ffma2(unsigned long long &acc, unsigned long long a, unsigned long long b) {
    asm("fma.rn.f32x2 %0, %1, %2, %0;" : "+l"(acc) : "l"(a), "l"(b));
}
__device__ __forceinline__ void fadd2(unsigned long long &acc, unsigned long long a) {
    asm("add.rn.f32x2 %0, %0, %1;" : "+l"(acc) : "l"(a));
}
__device__ __forceinline__ void unpack2(unsigned long long p, float &lo, float &hi) {
    asm("mov.b64 {%0, %1}, %2;" : "=f"(lo), "=f"(hi) : "l"(p));
}
__device__ __forceinline__ void cpa16(uint32_t s, const void* g) {
    asm volatile("cp.async.cg.shared.global [%0], [%1], 16;" :: "r"(s), "l"(g));
}
#define CP_COMMIT() asm volatile("cp.async.commit_group;" ::: "memory")
#define CP_WAIT1()  asm volatile("cp.async.wait_group 1;" ::: "memory")

#define MBARRIER_INIT(a, n) \
    asm volatile("mbarrier.init.shared.b64 [%0], %1;" :: "r"(a), "r"(n) : "memory")
#define MBARRIER_EXPECT_TX(a, tx) \
    asm volatile("mbarrier.arrive.expect_tx.shared.b64 _, [%0], %1;" :: "r"(a), "r"(tx) : "memory")
#define MBARRIER_ARRIVE(a) \
    asm volatile("mbarrier.arrive.release.cta.shared.b64 _, [%0];" :: "r"(a) : "memory")
#define MBARRIER_WAIT(a, ph) do { \
    asm volatile("{\n\t.reg .pred P;\n\tWL%=:\n\t" \
        "mbarrier.try_wait.parity.acquire.cta.shared::cta.b64 P, [%0], %1, 0x989680;\n\t" \
        "@P bra.uni WD%=;\n\tbra.uni WL%=;\n\tWD%=:\n\t}" \
        :: "r"(a), "r"(ph) : "memory"); \
} while (0)
#define TMA_LOAD_3D(smem_addr, map, cx, cy, cz, mbar) \
    asm volatile("cp.async.bulk.tensor.3d.shared::cta.global.tile.mbarrier::complete_tx::bytes " \
        "[%0], [%1, {%2, %3, %4}], [%5];" \
        :: "r"((uint32_t)(smem_addr)), "l"(map), "r"((int)(cx)), "r"((int)(cy)), "r"((int)(cz)), \
           "r"((uint32_t)(mbar)) : "memory")

// =====================================================================
// Kernel A (persistent, spill-safe): e[b,i,j] = exp(sum_h x*rel).
// grid=148. 256 thr = 32 j x (4 i-groups x 2 b-groups); thread tile
// 8i x 4b x FULL h -> acc = 32 f32x2 = 64 regs, epilogue is per-thread
// (no syncs, no scratch). 5-stage TMA ring, producer lookahead 4,
// rotating producer warp.
// =====================================================================
#define TIA 32
#define TJA 32
#define HCA 8
#define NTILES 1024
#define GRIDA 148
#define NSTAGE 5
#define LOOKAHEAD 4
#define REL_BYTES (TIA * TJA * HCA * 4)   // 32768
#define X_BYTES   (BB * TJA * HCA * 4)    // 8192
#define STAGE_BYTES (REL_BYTES + X_BYTES) // 40960
#define SMEMA (1024 + NSTAGE * STAGE_BYTES)   // 205824

__global__ void __launch_bounds__(256, 1)
scores_kernel(const __grid_constant__ CUtensorMap tmr,
              const __grid_constant__ CUtensorMap tmx,
              float* __restrict__ scores) {
    extern __shared__ __align__(1024) char sm[];
    const uint32_t sbase = (uint32_t)__cvta_generic_to_shared(sm);
    const uint32_t mb = sbase;
    const int t  = threadIdx.x;
    const int j  = t & 31;
    const int g  = t >> 5;
    const int ig = g & 3;        // i-group (8 rows)
    const int bg = g >> 2;       // b-group (4 batches)
    const int bid = blockIdx.x;
    const int jx = ((j >> 2) & 1) << 4;   // SW32 xor (const per thread)

    int ntiles = 0;
    for (int tile = bid; tile < NTILES; tile += GRIDA) ntiles++;
    const int total = ntiles * 16;

    if (t == 0) {
#pragma unroll
        for (int s = 0; s < NSTAGE; s++) {
            MBARRIER_INIT(mb + s * 16, 1);       // full
            MBARRIER_INIT(mb + s * 16 + 8, 256); // empty
        }
    }
    __syncthreads();

    // prologue: chunks 0..3 (tile = bid)
    if (t == 0) {
        const int i0p = (bid >> 5) * TIA, j0p = (bid & 31) * TJA;
#pragma unroll
        for (int n = 0; n < LOOKAHEAD; n++) {
            uint32_t fb = mb + n * 16;
            uint32_t dst = sbase + 1024 + n * STAGE_BYTES;
            MBARRIER_EXPECT_TX(fb, STAGE_BYTES);
            TMA_LOAD_3D(dst, &tmr, n * HCA, j0p, i0p, fb);
            TMA_LOAD_3D(dst + REL_BYTES, &tmx, n * HCA, j0p, 0, fb);
        }
    }

    unsigned long long acc[8][4] = {};    // 8 i x 4 b (f32x2 over h parity)

    int slot = 0, ph = 0;                 // consumer ring state
    int pslot = LOOKAHEAD, pk = 0, pep = 1;  // producer ring state (chunk cg+4)
    int cur_tile = bid;

    for (int cg = 0; cg < total; cg++) {
        MBARRIER_WAIT(mb + slot * 16, ph);

        const char* st = sm + 1024 + slot * STAGE_BYTES;
        const char* rb = st + ((ig * 8) * TJA + j) * 32;
        const char* xb = st + REL_BYTES + ((bg * 4) * TJA + j) * 32;

        // x: 4 b-rows x 32B (2 LDS.128 each) -> 32 regs
        ulonglong2 xa[4], xc[4];
#pragma unroll
        for (int q = 0; q < 4; q++) {
            xa[q] = *(const ulonglong2*)(xb + q * (TJA * 32) + jx);
            xc[q] = *(const ulonglong2*)(xb + q * (TJA * 32) + (16 ^ jx));
        }
        // rel rows streamed one at a time (transient regs)
#pragma unroll
        for (int p = 0; p < 8; p++) {
            ulonglong2 ra = *(const ulonglong2*)(rb + p * (TJA * 32) + jx);
            ulonglong2 rc = *(const ulonglong2*)(rb + p * (TJA * 32) + (16 ^ jx));
#pragma unroll
            for (int q = 0; q < 4; q++) {
                ffma2(acc[p][q], ra.x, xa[q].x);
                ffma2(acc[p][q], ra.y, xa[q].y);
                ffma2(acc[p][q], rc.x, xc[q].x);
                ffma2(acc[p][q], rc.y, xc[q].y);
            }
        }

        MBARRIER_ARRIVE(mb + slot * 16 + 8);

        // rotating producer: warp (cg&7) issues chunk n = cg+4 into pslot
        {
            const int n = cg + LOOKAHEAD;
            if (n < total && g == (cg & 7)) {
                MBARRIER_WAIT(mb + pslot * 16 + 8, pep);
                if (j == 0) {
                    const int tile_n = bid + (n >> 4) * GRIDA;
                    const int cn = n & 15;
                    const int i0n = (tile_n >> 5) * TIA, j0n = (tile_n & 31) * TJA;
                    uint32_t fb = mb + pslot * 16;
                    uint32_t dst = sbase + 1024 + pslot * STAGE_BYTES;
                    MBARRIER_EXPECT_TX(fb, STAGE_BYTES);
                    TMA_LOAD_3D(dst, &tmr, cn * HCA, j0n, i0n, fb);
                    TMA_LOAD_3D(dst + REL_BYTES, &tmx, cn * HCA, j0n, 0, fb);
                }
            }
        }

        if ((cg & 15) == 15) {
            // per-thread epilogue: no syncs, no smem
            const int i0 = (cur_tile >> 5) * TIA, j0 = (cur_tile & 31) * TJA;
#pragma unroll
            for (int p = 0; p < 8; p++) {
                const int i = i0 + ig * 8 + p;
#pragma unroll
                for (int q = 0; q < 4; q++) {
                    float lo, hi; unpack2(acc[p][q], lo, hi);
                    // no max-subtract: |score| <= ~70, exp safe in f32
                    scores[((size_t)(bg * 4 + q) * SS + i) * SS + j0 + j] = __expf(lo + hi);
                    acc[p][q] = 0ull;
                }
            }
            cur_tile += GRIDA;
        }

        // advance rings
        if (++slot == NSTAGE) { slot = 0; ph ^= 1; }
        if (++pslot == NSTAGE) { pslot = 0; pk++; pep ^= 1; }
    }
}

// ---------------- xT[b][h][j] = x[b][j][h] ----------------
__global__ void xT_kernel(const float* __restrict__ x, float* __restrict__ xT) {
    __shared__ float tile[32][33];
    const int b = blockIdx.z;
    const int j0 = blockIdx.x * 32, h0 = blockIdx.y * 32;
    const int tx = threadIdx.x, ty = threadIdx.y;   // (32, 8)
#pragma unroll
    for (int k = 0; k < 4; k++)
        tile[ty + k * 8][tx] = x[((size_t)b * SS + j0 + ty + k * 8) * HH + h0 + tx];
    __syncthreads();
#pragma unroll
    for (int k = 0; k < 4; k++)
        xT[((size_t)b * HH + h0 + ty + k * 8) * SS + j0 + tx] = tile[tx][ty + k * 8];
}

// =====================================================================
// Kernel B: out[b,i,h] = (sum_j e[b,i,j]*x[b,j,h]) / (sum_j e[b,i,j])
// Both operands j-contiguous (xT) -> natural f32x2 pairs, no pack movs.
// w smem reads are warp-broadcast. 256 thr, MTB=64, grid 16x8.
// =====================================================================
#define MTB 64
#define KTB 32
#define NCHB (SS / KTB)
#define WROW 36
#define XROW 36
#define WF (MTB * WROW)       // 2304 floats
#define XFB (HH * XROW)       // 4608 floats
#define BUFBF (WF + XFB)      // 6912 floats = 27648 B
#define NBUFB 3

__global__ void __launch_bounds__(256, 1)
out_kernel(const float* __restrict__ w,
           const float* __restrict__ xT,
           float* __restrict__ out) {
    extern __shared__ float smB[];
    const int t  = threadIdx.x;
    const int tx = t & 31;       // h-quad: rows tx*4..+3 of xT tile
    const int ty = t >> 5;       // i-group of 8
    const int b  = blockIdx.y;
    const int m0 = blockIdx.x * MTB;
    const float* wb = w + (size_t)b * SS * SS;
    const float* xb = xT + (size_t)b * HH * SS;
    const uint32_t sbase = (uint32_t)__cvta_generic_to_shared(smB);

    auto stage = [&](int c, int s) {
        uint32_t bbase = sbase + (uint32_t)s * (BUFBF * 4);
        // w: 64 i-rows x 8 float4 (32 j) = 512 f4
#pragma unroll
        for (int k = 0; k < 2; k++) {
            int idx = t + k * 256;
            int f4 = idx & 7, row = idx >> 3;
            cpa16(bbase + (uint32_t)(row * WROW + f4 * 4) * 4,
                  wb + (size_t)(m0 + row) * SS + c * KTB + f4 * 4);
        }
        // xT: 128 h-rows x 8 float4 (32 j) = 1024 f4
#pragma unroll
        for (int k = 0; k < 4; k++) {
            int idx = t + k * 256;
            int f4 = idx & 7, row = idx >> 3;
            cpa16(bbase + (uint32_t)(WF + row * XROW + f4 * 4) * 4,
                  xb + (size_t)row * SS + c * KTB + f4 * 4);
        }
    };

    stage(0, 0); CP_COMMIT();
    stage(1, 1); CP_COMMIT();

    unsigned long long acc2[8][4] = {};   // (even-j, odd-j) per (i,h)
    unsigned long long wsum2[8] = {};

    int buf = 0;
    for (int c = 0; c < NCHB; c++) {
        CP_WAIT1();
        __syncthreads();
        if (c + 2 < NCHB) {
            int nb = buf + 2; if (nb >= NBUFB) nb -= NBUFB;
            stage(c + 2, nb);
        }
        CP_COMMIT();

        const float* wsb = smB + (size_t)buf * BUFBF;
        const float* xsb = wsb + WF;
#pragma unroll
        for (int j4 = 0; j4 < KTB / 4; j4++) {
            ulonglong2 xq[4];
#pragma unroll
            for (int h = 0; h < 4; h++)
                xq[h] = *reinterpret_cast<const ulonglong2*>(xsb + (tx * 4 + h) * XROW + j4 * 4);
#pragma unroll
            for (int p = 0; p < 8; p++) {
                ulonglong2 wv = *reinterpret_cast<const ulonglong2*>(wsb + (ty * 8 + p) * WROW + j4 * 4);
                fadd2(wsum2[p], wv.x);
                fadd2(wsum2[p], wv.y);
#pragma unroll
                for (int h = 0; h < 4; h++) {
                    ffma2(acc2[p][h], wv.x, xq[h].x);
                    ffma2(acc2[p][h], wv.y, xq[h].y);
                }
            }
        }
        buf++; if (buf == NBUFB) buf = 0;
    }

#pragma unroll
    for (int p = 0; p < 8; p++) {
        float slo, shi; unpack2(wsum2[p], slo, shi);
        float inv = 1.0f / (slo + shi);
        float4 o;
        {
            float lo, hi;
            unpack2(acc2[p][0], lo, hi); o.x = (lo + hi) * inv;
            unpack2(acc2[p][1], lo, hi); o.y = (lo + hi) * inv;
            unpack2(acc2[p][2], lo, hi); o.z = (lo + hi) * inv;
            unpack2(acc2[p][3], lo, hi); o.w = (lo + hi) * inv;
        }
        *reinterpret_cast<float4*>(out + ((size_t)b * SS + m0 + ty * 8 + p) * HH + tx * 4) = o;
    }
}

// ---------------- launch ----------------
typedef CUresult (*EncodeFn)(CUtensorMap*, CUtensorMapDataType, cuuint32_t, void*,
                             const cuuint64_t*, const cuuint64_t*, const cuuint32_t*,
                             const cuuint32_t*, CUtensorMapInterleave, CUtensorMapSwizzle,
                             CUtensorMapL2promotion, CUtensorMapFloatOOBfill);

extern "C" void kernel_launch(void* const* d_in, const int* in_sizes, int n_in,
                              void* d_out, int out_size) {
    const float* x   = (const float*)d_in[0];   // (8, 1024, 128) f32
    const float* rel = (const float*)d_in[1];   // (1024, 1024, 128) f32
    float* out = (float*)d_out;

    float *scores = nullptr, *xT = nullptr;
    cudaGetSymbolAddress((void**)&scores, g_scores);
    cudaGetSymbolAddress((void**)&xT, g_xT);

    EncodeFn enc = nullptr;
    cudaDriverEntryPointQueryResult qr;
    cudaGetDriverEntryPoint("cuTensorMapEncodeTiled", (void**)&enc, cudaEnableDefault, &qr);

    CUtensorMap tmr, tmx;
    {
        cuuint64_t dims[3]    = {HH, SS, SS};
        cuuint64_t strides[2] = {HH * 4ull, (cuuint64_t)SS * HH * 4ull};
        cuuint32_t box[3]     = {HCA, TJA, TIA};
        cuuint32_t es[3]      = {1, 1, 1};
        enc(&tmr, CU_TENSOR_MAP_DATA_TYPE_FLOAT32, 3, (void*)rel, dims, strides, box, es,
            CU_TENSOR_MAP_INTERLEAVE_NONE, CU_TENSOR_MAP_SWIZZLE_32B,
            CU_TENSOR_MAP_L2_PROMOTION_L2_128B, CU_TENSOR_MAP_FLOAT_OOB_FILL_NONE);
    }
    {
        cuuint64_t dims[3]    = {HH, SS, BB};
        cuuint64_t strides[2] = {HH * 4ull, (cuuint64_t)SS * HH * 4ull};
        cuuint32_t box[3]     = {HCA, TJA, BB};
        cuuint32_t es[3]      = {1, 1, 1};
        enc(&tmx, CU_TENSOR_MAP_DATA_TYPE_FLOAT32, 3, (void*)x, dims, strides, box, es,
            CU_TENSOR_MAP_INTERLEAVE_NONE, CU_TENSOR_MAP_SWIZZLE_32B,
            CU_TENSOR_MAP_L2_PROMOTION_L2_128B, CU_TENSOR_MAP_FLOAT_OOB_FILL_NONE);
    }

    xT_kernel<<<dim3(SS / 32, HH / 32, BB), dim3(32, 8)>>>(x, xT);

    cudaFuncSetAttribute(scores_kernel, cudaFuncAttributeMaxDynamicSharedMemorySize, SMEMA);
    scores_kernel<<<GRIDA, 256, SMEMA>>>(tmr, tmx, scores);

    const int smB_bytes = NBUFB * BUFBF * 4;    // 82944
    cudaFuncSetAttribute(out_kernel, cudaFuncAttributeMaxDynamicSharedMemorySize, smB_bytes);
    out_kernel<<<dim3(SS / MTB, BB), 256, smB_bytes>>>(scores, xT, out);
}